// round 6
// baseline (speedup 1.0000x reference)
#include <cuda_runtime.h>

#define CCH 64
#define SS 409600
#define PL 16384
#define NTOT 26214400

__device__ float g_t[NTOT];
__device__ float g_attn[NTOT];
__device__ float g_x1[NTOT];
__device__ float g_bias[4 * 64 * 64];
__device__ float g_phw[64 * 16384];
__device__ float g_puv[64 * 25];
__device__ float g_phu[64 * 640];
__device__ float g_pvw[64 * 640];
__device__ float g_uvhw[64 * 17689];
__device__ float g_mhw[64 * 16384];
__device__ float g_muv[64 * 25];
__device__ float g_muh[64 * 640];
__device__ float g_mvw[64 * 640];
__device__ float g_y[104857600];
__device__ float g_z[104857600];

// LN over C of the external input x -> g_t
__global__ void k_ln1(const float* __restrict__ src, const float* __restrict__ w,
                      const float* __restrict__ b) {
    int pos = blockIdx.x * blockDim.x + threadIdx.x;
    if (pos >= SS) return;
    float v[CCH]; float s = 0.f, s2 = 0.f;
#pragma unroll
    for (int c = 0; c < CCH; c++) { float t = src[c * SS + pos]; v[c] = t; s += t; s2 += t * t; }
    float mu = s * (1.f / CCH);
    float inv = rsqrtf(s2 * (1.f / CCH) - mu * mu + 1e-5f);
#pragma unroll
    for (int c = 0; c < CCH; c++)
        g_t[c * SS + pos] = (v[c] - mu) * inv * __ldg(w + c) + __ldg(b + c);
}

// LN over C of g_x1 -> g_t
__global__ void k_ln2(const float* __restrict__ w, const float* __restrict__ b) {
    int pos = blockIdx.x * blockDim.x + threadIdx.x;
    if (pos >= SS) return;
    float v[CCH]; float s = 0.f, s2 = 0.f;
#pragma unroll
    for (int c = 0; c < CCH; c++) { float t = g_x1[c * SS + pos]; v[c] = t; s += t; s2 += t * t; }
    float mu = s * (1.f / CCH);
    float inv = rsqrtf(s2 * (1.f / CCH) - mu * mu + 1e-5f);
#pragma unroll
    for (int c = 0; c < CCH; c++)
        g_t[c * SS + pos] = (v[c] - mu) * inv * __ldg(w + c) + __ldg(b + c);
}

__global__ void k_bias(const float* __restrict__ rpb, const int* __restrict__ rpi) {
    int idx = blockIdx.x * 256 + threadIdx.x;
    if (idx >= 16384) return;
    int h = idx >> 12, r = idx & 4095, j = r >> 6, q = r & 63;
    g_bias[idx] = rpb[rpi[q * 64 + j] * 4 + h];
}

// one block per 8x8 window; shift folded into (coord+124)&127 on load AND store
__global__ void k_attn(const float* __restrict__ qkvw, const float* __restrict__ qkvb,
                       const float* __restrict__ pw, const float* __restrict__ pb) {
    extern __shared__ float sm[];
    const int QP = 193, XP = 65;
    float* qkv_s = sm;               // 64 x 193
    float* xw_s = sm + 64 * QP;      // 64 x 65
    int wid = blockIdx.x;
    int wb = wid & 15, hb = (wid >> 4) & 15, v = (wid >> 8) % 5, u = wid / 1280;
    int tid = threadIdx.x;
    int base_uv = u * 81920 + v * 16384;
    for (int i = tid; i < 4096; i += 256) {
        int ch = i >> 6, tok = i & 63;
        int h = (hb * 8 + (tok >> 3) + 124) & 127;
        int w = (wb * 8 + (tok & 7) + 124) & 127;
        xw_s[tok * XP + ch] = g_t[ch * SS + base_uv + h * 128 + w];
    }
    __syncthreads();
    int tok = tid & 63, ob = tid >> 6;
    for (int i = 0; i < 48; i++) {
        int oc = ob + i * 4;
        float acc = __ldg(qkvb + oc);
#pragma unroll
        for (int c = 0; c < 64; c++) acc += xw_s[tok * XP + c] * __ldg(qkvw + oc * 64 + c);
        if ((oc % 48) < 16) acc *= 0.25f;
        qkv_s[tok * QP + oc] = acc;
    }
    __syncthreads();
    {
        int head = ob, q = tok;
        float qreg[16];
#pragma unroll
        for (int d = 0; d < 16; d++) qreg[d] = qkv_s[q * QP + head * 48 + d];
        float m = -1e30f, Z = 0.f, acc[16];
#pragma unroll
        for (int d = 0; d < 16; d++) acc[d] = 0.f;
        const float* bh = g_bias + head * 4096;
        for (int j = 0; j < 64; j++) {
            float s = __ldg(bh + j * 64 + q);
            const float* kr = qkv_s + j * QP + head * 48 + 16;
#pragma unroll
            for (int d = 0; d < 16; d++) s += qreg[d] * kr[d];
            float mn = fmaxf(m, s);
            float corr = __expf(m - mn), p = __expf(s - mn);
            Z = Z * corr + p;
#pragma unroll
            for (int d = 0; d < 16; d++) acc[d] = acc[d] * corr + p * kr[16 + d];
            m = mn;
        }
        float iz = 1.f / Z;
#pragma unroll
        for (int d = 0; d < 16; d++) xw_s[q * XP + head * 16 + d] = acc[d] * iz;
    }
    __syncthreads();
#pragma unroll 4
    for (int i = 0; i < 16; i++) {
        int oc = ob + i * 4;
        float a = __ldg(pb + oc);
#pragma unroll
        for (int k = 0; k < 64; k++) a += xw_s[tok * XP + k] * __ldg(pw + oc * 64 + k);
        int h = (hb * 8 + (tok >> 3) + 124) & 127;
        int w = (wb * 8 + (tok & 7) + 124) & 127;
        g_attn[oc * SS + base_uv + h * 128 + w] = a;
    }
}

__global__ void k_pool_hw() {
    int i = blockIdx.x * 256 + threadIdx.x;
    if (i >= 64 * PL) return;
    int c = i >> 14, p = i & (PL - 1);
    float s = 0.f;
#pragma unroll
    for (int uv = 0; uv < 25; uv++) s += g_t[c * SS + uv * PL + p];
    g_phw[i] = s * (1.f / 25.f);
}
__global__ void k_pool_uv() {
    __shared__ float red[256];
    int b = blockIdx.x;
    const float4* base = (const float4*)(g_t + b * PL);
    float s = 0.f;
    for (int i = threadIdx.x; i < PL / 4; i += 256) {
        float4 a = base[i]; s += a.x + a.y + a.z + a.w;
    }
    red[threadIdx.x] = s; __syncthreads();
    for (int st = 128; st > 0; st >>= 1) {
        if (threadIdx.x < st) red[threadIdx.x] += red[threadIdx.x + st];
        __syncthreads();
    }
    if (threadIdx.x == 0) g_puv[b] = red[0] * (1.f / PL);
}
__global__ void k_pool_hu() {  // [c][h][u] mean over (v,w)
    int i = blockIdx.x * 256 + threadIdx.x;
    if (i >= 64 * 640) return;
    int u = i % 5, h = (i / 5) & 127, c = i / 640;
    float s = 0.f;
    for (int v = 0; v < 5; v++) {
        const float4* row = (const float4*)(g_t + c * SS + u * 81920 + v * PL + h * 128);
#pragma unroll
        for (int k = 0; k < 32; k++) { float4 a = row[k]; s += a.x + a.y + a.z + a.w; }
    }
    g_phu[i] = s * (1.f / 640.f);
}
__global__ void k_pool_vw() {  // [c][v][w] mean over (u,h)
    int i = blockIdx.x * 256 + threadIdx.x;
    if (i >= 64 * 640) return;
    int w = i & 127, v = (i >> 7) % 5, c = i / 640;
    float s = 0.f;
    for (int u = 0; u < 5; u++) {
        const float* base = g_t + c * SS + u * 81920 + v * PL + w;
        for (int h = 0; h < 128; h++) s += base[h * 128];
    }
    g_pvw[i] = s * (1.f / 640.f);
}

__global__ void k_mca_conv(const float* __restrict__ w1, const float* __restrict__ b1,
                           const float* __restrict__ w2, const float* __restrict__ b2) {
    __shared__ float ins[4160];   // 64 x 65
    __shared__ float y1s[4160];   // 64 x 65
    int tid = threadIdx.x;
    int p0 = blockIdx.x * 64;
    for (int i = tid; i < 4096; i += 256) {
        int c = i >> 6, pl = i & 63, px = p0 + pl;
        float val = 0.f;
        if (px < 17689) {
            int r = px / 133, col = px - r * 133;
            if (r < 128) val = (col < 128) ? g_phw[c * PL + r * 128 + col]
                                           : g_phu[c * 640 + r * 5 + (col - 128)];
            else         val = (col < 128) ? g_pvw[c * 640 + (r - 128) * 128 + col]
                                           : g_puv[c * 25 + (col - 128) * 5 + (r - 128)];
        }
        ins[c * 65 + pl] = val;
    }
    __syncthreads();
    int pl = tid & 63, cb = tid >> 6;
    float yv[16];
#pragma unroll
    for (int i = 0; i < 16; i++) {
        int oc = cb + i * 4;
        float a = __ldg(b1 + oc);
#pragma unroll
        for (int c = 0; c < 64; c++) a += __ldg(w1 + oc * 64 + c) * ins[c * 65 + pl];
        yv[i] = a / (1.f + __expf(-a));
    }
#pragma unroll
    for (int i = 0; i < 16; i++) y1s[(cb + i * 4) * 65 + pl] = yv[i];
    __syncthreads();
    int px = p0 + pl;
#pragma unroll
    for (int i = 0; i < 16; i++) {
        int oc = cb + i * 4;
        float a = __ldg(b2 + oc);
#pragma unroll
        for (int c = 0; c < 64; c++) a += __ldg(w2 + oc * 64 + c) * y1s[c * 65 + pl];
        if (px < 17689) g_uvhw[oc * 17689 + px] = a;
    }
}

__global__ void k_mca_fuse(const float* __restrict__ fw, const float* __restrict__ fb) {
    __shared__ float ins[4160];   // 64 x 65
    int b = blockIdx.x, tid = threadIdx.x;
    int type, p0, npx;
    if (b < 256)       { type = 0; p0 = b * 64;         npx = 16384; }
    else if (b == 256) { type = 1; p0 = 0;              npx = 25; }
    else if (b < 267)  { type = 2; p0 = (b - 257) * 64; npx = 640; }
    else               { type = 3; p0 = (b - 267) * 64; npx = 640; }
    const float* wt = fw + type * 4096;
    for (int i = tid; i < 4096; i += 256) {
        int c = i >> 6, pl = i & 63, px = p0 + pl;
        float v = 0.f;
        if (px < npx) {
            int r, col;
            if (type == 0)      { r = px >> 7;         col = px & 127; }
            else if (type == 1) { r = 128 + (px % 5);  col = 128 + (px / 5); }
            else if (type == 2) { r = px & 127;        col = 128 + (px >> 7); }
            else                { r = 128 + (px >> 7); col = px & 127; }
            v = g_uvhw[c * 17689 + r * 133 + col];
        }
        ins[c * 65 + pl] = v;
    }
    __syncthreads();
    int pl = tid & 63, cb = tid >> 6, px = p0 + pl;
    float* outp = (type == 0) ? g_mhw : (type == 1) ? g_muv : (type == 2) ? g_muh : g_mvw;
#pragma unroll
    for (int i = 0; i < 16; i++) {
        int oc = cb + i * 4;
        float a = __ldg(fb + type * 64 + oc);
#pragma unroll
        for (int c = 0; c < 64; c++) a += __ldg(wt + oc * 64 + c) * ins[c * 65 + pl];
        if (px < npx) outp[oc * npx + px] = a;
    }
}

__global__ void k_add(const float* __restrict__ x) {
    int i4 = blockIdx.x * 256 + threadIdx.x;
    if (i4 >= NTOT / 4) return;
    int e = i4 * 4;
    int c = e / SS, rem = e - c * SS;
    int u = rem / 81920, rem2 = rem - u * 81920;
    int vv = rem2 / PL, p = rem2 - vv * PL;
    int h = p >> 7, w = p & 127;
    float4 xv = *(const float4*)(x + e);
    float4 av = *(const float4*)(g_attn + e);
    float4 tv = *(const float4*)(g_t + e);
    float4 hwv = *(const float4*)(g_mhw + c * PL + p);
    float4 vwv = *(const float4*)(g_mvw + c * 640 + vv * 128 + w);
    float sc = g_muv[c * 25 + u * 5 + vv] + g_muh[c * 640 + u * 128 + h];
    float4 o;
    o.x = xv.x + av.x + tv.x * (hwv.x + vwv.x + sc);
    o.y = xv.y + av.y + tv.y * (hwv.y + vwv.y + sc);
    o.z = xv.z + av.z + tv.z * (hwv.z + vwv.z + sc);
    o.w = xv.w + av.w + tv.w * (hwv.w + vwv.w + sc);
    *(float4*)(g_x1 + e) = o;
}

// mbconv: plane P = n*64+cc of the 6D tensor (reshape = reinterpretation)
__global__ void k_expand(const float* __restrict__ w1, const float* __restrict__ b1) {
    __shared__ float ins[64 * 68];
    int b = blockIdx.x;
    int uv = b >> 8, p0 = (b & 255) * 64;
    int tid = threadIdx.x;
    for (int i = tid; i < 1024; i += 256) {
        int c = i >> 4, pl4 = i & 15;
        *(float4*)(ins + c * 68 + pl4 * 4) =
            *(const float4*)(g_t + (uv * 64 + c) * PL + p0 + pl4 * 4);
    }
    __syncthreads();
    int pg = tid & 15, og = tid >> 4;
    float acc[16][4];
#pragma unroll
    for (int i = 0; i < 16; i++) acc[i][0] = acc[i][1] = acc[i][2] = acc[i][3] = 0.f;
    const float* wrow = w1 + og * 16 * 64;
#pragma unroll 4
    for (int c = 0; c < 64; c++) {
        float4 iv = *(const float4*)(ins + c * 68 + pg * 4);
#pragma unroll
        for (int i = 0; i < 16; i++) {
            float wv = __ldg(wrow + i * 64 + c);
            acc[i][0] += wv * iv.x; acc[i][1] += wv * iv.y;
            acc[i][2] += wv * iv.z; acc[i][3] += wv * iv.w;
        }
    }
    float* ybase = g_y + (uv * 256 + og * 16) * PL + p0 + pg * 4;
#pragma unroll
    for (int i = 0; i < 16; i++) {
        float bb = __ldg(b1 + og * 16 + i);
        float4 o; float a;
        a = acc[i][0] + bb; o.x = a / (1.f + __expf(-a));
        a = acc[i][1] + bb; o.y = a / (1.f + __expf(-a));
        a = acc[i][2] + bb; o.z = a / (1.f + __expf(-a));
        a = acc[i][3] + bb; o.w = a / (1.f + __expf(-a));
        *(float4*)(ybase + i * PL) = o;
    }
}

__global__ void k_dw(const float* __restrict__ dw, const float* __restrict__ db) {
    __shared__ float tile[12][132];
    int b = blockIdx.x;
    int plane = b >> 4, h0 = (b & 15) * 8;
    int ch = plane & 255;
    const float* src = g_y + plane * PL;
    int tid = threadIdx.x;
    for (int i = tid; i < 12 * 132; i += 256) {
        int rr = i / 132, cc = i % 132;
        int h = h0 + rr - 2, w = cc - 2;
        tile[rr][cc] = (h >= 0 && h < 128 && w >= 0 && w < 128) ? src[h * 128 + w] : 0.f;
    }
    __syncthreads();
    float wr[25];
#pragma unroll
    for (int k = 0; k < 25; k++) wr[k] = __ldg(dw + ch * 25 + k);
    float bb = __ldg(db + ch);
    int w = tid & 127, hs = tid >> 7;
    for (int r = hs; r < 8; r += 2) {
        float a = bb;
#pragma unroll
        for (int dy = 0; dy < 5; dy++)
#pragma unroll
            for (int dx = 0; dx < 5; dx++)
                a += wr[dy * 5 + dx] * tile[r + dy][w + dx];
        g_z[plane * PL + (h0 + r) * 128 + w] = a / (1.f + __expf(-a));
    }
}

__global__ void k_proj(const float* __restrict__ w2, const float* __restrict__ b2,
                       float* __restrict__ out) {
    __shared__ float ins[64 * 132];
    int b = blockIdx.x;
    int uv = b >> 7, p0 = (b & 127) * 128;
    int tid = threadIdx.x;
    int pg = tid & 31, og = tid >> 5;
    float acc[8][4];
#pragma unroll
    for (int i = 0; i < 8; i++) acc[i][0] = acc[i][1] = acc[i][2] = acc[i][3] = 0.f;
    for (int kc = 0; kc < 4; kc++) {
        __syncthreads();
        for (int i = tid; i < 2048; i += 256) {
            int k = i >> 5, pl4 = i & 31;
            *(float4*)(ins + k * 132 + pl4 * 4) =
                *(const float4*)(g_z + (uv * 256 + kc * 64 + k) * PL + p0 + pl4 * 4);
        }
        __syncthreads();
#pragma unroll 4
        for (int k = 0; k < 64; k++) {
            float4 iv = *(const float4*)(ins + k * 132 + pg * 4);
#pragma unroll
            for (int i = 0; i < 8; i++) {
                float wv = __ldg(w2 + (og * 8 + i) * 256 + kc * 64 + k);
                acc[i][0] += wv * iv.x; acc[i][1] += wv * iv.y;
                acc[i][2] += wv * iv.z; acc[i][3] += wv * iv.w;
            }
        }
    }
#pragma unroll
    for (int i = 0; i < 8; i++) {
        int oc = og * 8 + i;
        float bb = __ldg(b2 + oc);
        int g = (uv * 64 + oc) * PL + p0 + pg * 4;
        float4 xv = *(const float4*)(g_x1 + g);
        float4 o;
        o.x = acc[i][0] + bb + xv.x; o.y = acc[i][1] + bb + xv.y;
        o.z = acc[i][2] + bb + xv.z; o.w = acc[i][3] + bb + xv.w;
        *(float4*)(out + g) = o;
    }
}

extern "C" void kernel_launch(void* const* d_in, const int* in_sizes, int n_in,
                              void* d_out, int out_size) {
    (void)in_sizes; (void)n_in; (void)out_size;
    const float* x    = (const float*)d_in[0];
    const float* n1w  = (const float*)d_in[1];
    const float* n1b  = (const float*)d_in[2];
    const float* n2w  = (const float*)d_in[3];
    const float* n2b  = (const float*)d_in[4];
    const float* qkvw = (const float*)d_in[5];
    const float* qkvb = (const float*)d_in[6];
    const float* pw   = (const float*)d_in[7];
    const float* pb   = (const float*)d_in[8];
    const float* rpb  = (const float*)d_in[9];
    const int*   rpi  = (const int*)d_in[10];
    const float* mw1  = (const float*)d_in[11];
    const float* mb1  = (const float*)d_in[12];
    const float* mw2  = (const float*)d_in[13];
    const float* mb2  = (const float*)d_in[14];
    const float* mfw  = (const float*)d_in[15];
    const float* mfb  = (const float*)d_in[16];
    const float* ew1  = (const float*)d_in[17];
    const float* eb1  = (const float*)d_in[18];
    const float* edw  = (const float*)d_in[19];
    const float* edb  = (const float*)d_in[20];
    const float* ew2  = (const float*)d_in[21];
    const float* eb2  = (const float*)d_in[22];
    float* out = (float*)d_out;

    cudaFuncSetAttribute(k_attn, cudaFuncAttributeMaxDynamicSharedMemorySize, 66048);

    k_bias<<<64, 256>>>(rpb, rpi);
    k_ln1<<<1600, 256>>>(x, n1w, n1b);
    k_attn<<<6400, 256, 66048>>>(qkvw, qkvb, pw, pb);
    k_pool_hw<<<4096, 256>>>();
    k_pool_uv<<<1600, 256>>>();
    k_pool_hu<<<160, 256>>>();
    k_pool_vw<<<160, 256>>>();
    k_mca_conv<<<277, 256>>>(mw1, mb1, mw2, mb2);
    k_mca_fuse<<<277, 256>>>(mfw, mfb);
    k_add<<<25600, 256>>>(x);
    k_ln2<<<1600, 256>>>(n2w, n2b);
    k_expand<<<6400, 256>>>(ew1, eb1);
    k_dw<<<102400, 256>>>(edw, edb);
    k_proj<<<3200, 256>>>(ew2, eb2, out);
}

// round 7
// speedup vs baseline: 1.4704x; 1.4704x over previous
#include <cuda_runtime.h>

#define CCH 64
#define SS 409600
#define PL 16384
#define NTOT 26214400
#define XP 68
#define WP 65

__device__ float g_t[NTOT];
__device__ float g_attn[NTOT];
__device__ float g_x1[NTOT];
__device__ float g_bias[4 * 64 * 64];
__device__ float g_phw[64 * 16384];
__device__ float g_puv[64 * 25];
__device__ float g_phu[64 * 640];
__device__ float g_pvw[64 * 640];
__device__ float g_uvhw[64 * 17689];
__device__ float g_mhw[64 * 16384];
__device__ float g_muv[64 * 25];
__device__ float g_muh[64 * 640];
__device__ float g_mvw[64 * 640];
__device__ float g_y[104857600];
__device__ float g_z[104857600];

__global__ void k_ln1(const float* __restrict__ src, const float* __restrict__ w,
                      const float* __restrict__ b) {
    int pos = blockIdx.x * blockDim.x + threadIdx.x;
    if (pos >= SS) return;
    float v[CCH]; float s = 0.f, s2 = 0.f;
#pragma unroll
    for (int c = 0; c < CCH; c++) { float t = src[c * SS + pos]; v[c] = t; s += t; s2 += t * t; }
    float mu = s * (1.f / CCH);
    float inv = rsqrtf(s2 * (1.f / CCH) - mu * mu + 1e-5f);
#pragma unroll
    for (int c = 0; c < CCH; c++)
        g_t[c * SS + pos] = (v[c] - mu) * inv * __ldg(w + c) + __ldg(b + c);
}

__global__ void k_bias(const float* __restrict__ rpb, const int* __restrict__ rpi) {
    int idx = blockIdx.x * 256 + threadIdx.x;
    if (idx >= 16384) return;
    int h = idx >> 12, r = idx & 4095, j = r >> 6, q = r & 63;
    g_bias[idx] = rpb[rpi[q * 64 + j] * 4 + h];
}

// smem (floats): xw_s [0,4352) 64x68 | qkv_s [4352,17408) 192x68 | w_s [17408,23648) 96x65
// total 23648 floats = 94592 B (dynamic). 2 blocks/SM.
__global__ void k_attn(const float* __restrict__ qkvw, const float* __restrict__ qkvb,
                       const float* __restrict__ pw, const float* __restrict__ pb) {
    extern __shared__ float sm[];
    float* xw_s = sm;
    float* qkv_s = sm + 4352;
    float* w_s = sm + 17408;
    int wid = blockIdx.x;
    int wb = wid & 15, hb = (wid >> 4) & 15, v = (wid >> 8) % 5, u = wid / 1280;
    int tid = threadIdx.x;
    int base = u * 81920 + v * 16384;
    // A: window load into xw_s[c][tok] via float4 (tok groups of 4 are gmem-contiguous)
    for (int i = tid; i < 1024; i += 256) {
        int c = i >> 4, tg4 = i & 15;
        int ty = tg4 >> 1, tx0 = (tg4 & 1) * 4;
        int h = (hb * 8 + ty + 124) & 127;
        int w = (wb * 8 + tx0 + 124) & 127;
        *(float4*)(xw_s + c * XP + tg4 * 4) =
            *(const float4*)(g_t + c * SS + base + h * 128 + w);
    }
    // stage qkv weights rows 0..95
    for (int i = tid; i < 6144; i += 256) {
        int oc = i >> 6, c = i & 63;
        w_s[oc * WP + c] = qkvw[i];
    }
    __syncthreads();
    int tg = tid & 15, og = tid >> 4;
    // B: qkv gemm, two passes of 96 output channels, acc tile 6 oc x 4 tok
#pragma unroll 1
    for (int pass = 0; pass < 2; pass++) {
        float acc[6][4];
#pragma unroll
        for (int o = 0; o < 6; o++) acc[o][0] = acc[o][1] = acc[o][2] = acc[o][3] = 0.f;
#pragma unroll 16
        for (int c = 0; c < 64; c++) {
            float4 xv = *(float4*)(xw_s + c * XP + tg * 4);
#pragma unroll
            for (int o = 0; o < 6; o++) {
                float wv = w_s[(og * 6 + o) * WP + c];
                acc[o][0] += wv * xv.x; acc[o][1] += wv * xv.y;
                acc[o][2] += wv * xv.z; acc[o][3] += wv * xv.w;
            }
        }
#pragma unroll
        for (int o = 0; o < 6; o++) {
            int oc = pass * 96 + og * 6 + o;
            float bb = __ldg(qkvb + oc);
            float sc = ((oc % 48) < 16) ? 0.25f : 1.f;
            float4 r;
            r.x = (acc[o][0] + bb) * sc; r.y = (acc[o][1] + bb) * sc;
            r.z = (acc[o][2] + bb) * sc; r.w = (acc[o][3] + bb) * sc;
            *(float4*)(qkv_s + oc * XP + tg * 4) = r;
        }
        if (pass == 0) {
            __syncthreads();
            for (int i = tid; i < 6144; i += 256) {
                int oc = i >> 6, c = i & 63;
                w_s[oc * WP + c] = qkvw[6144 + i];
            }
            __syncthreads();
        }
    }
    __syncthreads();
    // C: load proj weights (w_s free) + flash core; core writes into xw_s (free)
    for (int i = tid; i < 4096; i += 256) {
        int oc = i >> 6, c = i & 63;
        w_s[oc * WP + c] = pw[i];
    }
    {
        int head = tid >> 6, q = tid & 63;
        const float* qp = qkv_s + (head * 48) * XP + q;
        float qreg[16];
#pragma unroll
        for (int d = 0; d < 16; d++) qreg[d] = qp[d * XP];
        float m = -1e30f, Z = 0.f, acc[16];
#pragma unroll
        for (int d = 0; d < 16; d++) acc[d] = 0.f;
        const float* bh = g_bias + head * 4096;
        const float* kbase = qkv_s + (head * 48 + 16) * XP;
#pragma unroll 1
        for (int j = 0; j < 64; j++) {
            float s = __ldg(bh + j * 64 + q);
            const float* kr = kbase + j;
#pragma unroll
            for (int d = 0; d < 16; d++) s += qreg[d] * kr[d * XP];
            float mn = fmaxf(m, s);
            float corr = __expf(m - mn), p = __expf(s - mn);
            Z = Z * corr + p;
            const float* vr = kr + 16 * XP;
#pragma unroll
            for (int d = 0; d < 16; d++) acc[d] = acc[d] * corr + p * vr[d * XP];
            m = mn;
        }
        float iz = 1.f / Z;
#pragma unroll
        for (int d = 0; d < 16; d++) xw_s[(head * 16 + d) * XP + q] = acc[d] * iz;
    }
    __syncthreads();
    // D: proj gemm, acc tile 4 oc x 4 tok, vectorized store with shift-wrapped coords
    {
        float acc[4][4];
#pragma unroll
        for (int o = 0; o < 4; o++) acc[o][0] = acc[o][1] = acc[o][2] = acc[o][3] = 0.f;
#pragma unroll 16
        for (int c = 0; c < 64; c++) {
            float4 xv = *(float4*)(xw_s + c * XP + tg * 4);
#pragma unroll
            for (int o = 0; o < 4; o++) {
                float wv = w_s[(og * 4 + o) * WP + c];
                acc[o][0] += wv * xv.x; acc[o][1] += wv * xv.y;
                acc[o][2] += wv * xv.z; acc[o][3] += wv * xv.w;
            }
        }
        int ty = tg >> 1, tx0 = (tg & 1) * 4;
        int h = (hb * 8 + ty + 124) & 127;
        int w = (wb * 8 + tx0 + 124) & 127;
        float* op = g_attn + base + h * 128 + w;
#pragma unroll
        for (int o = 0; o < 4; o++) {
            int oc = og * 4 + o;
            float bb = __ldg(pb + oc);
            float4 r;
            r.x = acc[o][0] + bb; r.y = acc[o][1] + bb;
            r.z = acc[o][2] + bb; r.w = acc[o][3] + bb;
            *(float4*)(op + oc * SS) = r;
        }
    }
}

__global__ void k_pool_hw() {
    int i = blockIdx.x * 256 + threadIdx.x;
    if (i >= 64 * PL) return;
    int c = i >> 14, p = i & (PL - 1);
    float s = 0.f;
#pragma unroll
    for (int uv = 0; uv < 25; uv++) s += g_t[c * SS + uv * PL + p];
    g_phw[i] = s * (1.f / 25.f);
}
__global__ void k_pool_uv() {
    __shared__ float red[256];
    int b = blockIdx.x;
    const float4* base = (const float4*)(g_t + b * PL);
    float s = 0.f;
    for (int i = threadIdx.x; i < PL / 4; i += 256) {
        float4 a = base[i]; s += a.x + a.y + a.z + a.w;
    }
    red[threadIdx.x] = s; __syncthreads();
    for (int st = 128; st > 0; st >>= 1) {
        if (threadIdx.x < st) red[threadIdx.x] += red[threadIdx.x + st];
        __syncthreads();
    }
    if (threadIdx.x == 0) g_puv[b] = red[0] * (1.f / PL);
}
__global__ void k_pool_hu() {
    int i = blockIdx.x * 256 + threadIdx.x;
    if (i >= 64 * 640) return;
    int u = i % 5, h = (i / 5) & 127, c = i / 640;
    float s = 0.f;
    for (int v = 0; v < 5; v++) {
        const float4* row = (const float4*)(g_t + c * SS + u * 81920 + v * PL + h * 128);
#pragma unroll
        for (int k = 0; k < 32; k++) { float4 a = row[k]; s += a.x + a.y + a.z + a.w; }
    }
    g_phu[i] = s * (1.f / 640.f);
}
__global__ void k_pool_vw() {
    int i = blockIdx.x * 256 + threadIdx.x;
    if (i >= 64 * 640) return;
    int w = i & 127, v = (i >> 7) % 5, c = i / 640;
    float s = 0.f;
    for (int u = 0; u < 5; u++) {
        const float* base = g_t + c * SS + u * 81920 + v * PL + w;
        for (int h = 0; h < 128; h++) s += base[h * 128];
    }
    g_pvw[i] = s * (1.f / 640.f);
}

__global__ void k_mca_conv(const float* __restrict__ w1, const float* __restrict__ b1,
                           const float* __restrict__ w2, const float* __restrict__ b2) {
    __shared__ float ins[4160];
    __shared__ float y1s[4160];
    int tid = threadIdx.x;
    int p0 = blockIdx.x * 64;
    for (int i = tid; i < 4096; i += 256) {
        int c = i >> 6, pl = i & 63, px = p0 + pl;
        float val = 0.f;
        if (px < 17689) {
            int r = px / 133, col = px - r * 133;
            if (r < 128) val = (col < 128) ? g_phw[c * PL + r * 128 + col]
                                           : g_phu[c * 640 + r * 5 + (col - 128)];
            else         val = (col < 128) ? g_pvw[c * 640 + (r - 128) * 128 + col]
                                           : g_puv[c * 25 + (col - 128) * 5 + (r - 128)];
        }
        ins[c * 65 + pl] = val;
    }
    __syncthreads();
    int pl = tid & 63, cb = tid >> 6;
    float yv[16];
#pragma unroll
    for (int i = 0; i < 16; i++) {
        int oc = cb + i * 4;
        float a = __ldg(b1 + oc);
#pragma unroll
        for (int c = 0; c < 64; c++) a += __ldg(w1 + oc * 64 + c) * ins[c * 65 + pl];
        yv[i] = a / (1.f + __expf(-a));
    }
#pragma unroll
    for (int i = 0; i < 16; i++) y1s[(cb + i * 4) * 65 + pl] = yv[i];
    __syncthreads();
    int px = p0 + pl;
#pragma unroll
    for (int i = 0; i < 16; i++) {
        int oc = cb + i * 4;
        float a = __ldg(b2 + oc);
#pragma unroll
        for (int c = 0; c < 64; c++) a += __ldg(w2 + oc * 64 + c) * y1s[c * 65 + pl];
        if (px < 17689) g_uvhw[oc * 17689 + px] = a;
    }
}

__global__ void k_mca_fuse(const float* __restrict__ fw, const float* __restrict__ fb) {
    __shared__ float ins[4160];
    int b = blockIdx.x, tid = threadIdx.x;
    int type, p0, npx;
    if (b < 256)       { type = 0; p0 = b * 64;         npx = 16384; }
    else if (b == 256) { type = 1; p0 = 0;              npx = 25; }
    else if (b < 267)  { type = 2; p0 = (b - 257) * 64; npx = 640; }
    else               { type = 3; p0 = (b - 267) * 64; npx = 640; }
    const float* wt = fw + type * 4096;
    for (int i = tid; i < 4096; i += 256) {
        int c = i >> 6, pl = i & 63, px = p0 + pl;
        float v = 0.f;
        if (px < npx) {
            int r, col;
            if (type == 0)      { r = px >> 7;         col = px & 127; }
            else if (type == 1) { r = 128 + (px % 5);  col = 128 + (px / 5); }
            else if (type == 2) { r = px & 127;        col = 128 + (px >> 7); }
            else                { r = 128 + (px >> 7); col = px & 127; }
            v = g_uvhw[c * 17689 + r * 133 + col];
        }
        ins[c * 65 + pl] = v;
    }
    __syncthreads();
    int pl = tid & 63, cb = tid >> 6, px = p0 + pl;
    float* outp = (type == 0) ? g_mhw : (type == 1) ? g_muv : (type == 2) ? g_muh : g_mvw;
#pragma unroll
    for (int i = 0; i < 16; i++) {
        int oc = cb + i * 4;
        float a = __ldg(fb + type * 64 + oc);
#pragma unroll
        for (int c = 0; c < 64; c++) a += __ldg(wt + oc * 64 + c) * ins[c * 65 + pl];
        if (px < npx) outp[oc * npx + px] = a;
    }
}

// fused: x1 = x + attn + t*gates ; then LN(x1) -> g_t (x1 kept in registers)
__global__ void k_addln(const float* __restrict__ x, const float* __restrict__ w,
                        const float* __restrict__ b) {
    int pos = blockIdx.x * blockDim.x + threadIdx.x;
    if (pos >= SS) return;
    int u = pos / 81920, rem = pos - u * 81920;
    int vv = rem / PL, p = rem - vv * PL;
    int h = p >> 7, ww = p & 127;
    float x1v[CCH]; float s = 0.f, s2 = 0.f;
#pragma unroll
    for (int c = 0; c < CCH; c++) {
        float gate = g_mhw[c * PL + p] + g_mvw[c * 640 + vv * 128 + ww]
                   + g_muv[c * 25 + u * 5 + vv] + g_muh[c * 640 + u * 128 + h];
        float t = g_t[c * SS + pos];
        float val = x[c * SS + pos] + g_attn[c * SS + pos] + t * gate;
        x1v[c] = val; s += val; s2 += val * val;
        g_x1[c * SS + pos] = val;
    }
    float mu = s * (1.f / CCH);
    float inv = rsqrtf(s2 * (1.f / CCH) - mu * mu + 1e-5f);
#pragma unroll
    for (int c = 0; c < CCH; c++)
        g_t[c * SS + pos] = (x1v[c] - mu) * inv * __ldg(w + c) + __ldg(b + c);
}

// mbconv: plane P = n*64+cc of the 6D tensor (reshape = reinterpretation)
__global__ void k_expand(const float* __restrict__ w1, const float* __restrict__ b1) {
    __shared__ float ins[64 * 68];
    int b = blockIdx.x;
    int uv = b >> 8, p0 = (b & 255) * 64;
    int tid = threadIdx.x;
    for (int i = tid; i < 1024; i += 256) {
        int c = i >> 4, pl4 = i & 15;
        *(float4*)(ins + c * 68 + pl4 * 4) =
            *(const float4*)(g_t + (uv * 64 + c) * PL + p0 + pl4 * 4);
    }
    __syncthreads();
    int pg = tid & 15, og = tid >> 4;
    float acc[16][4];
#pragma unroll
    for (int i = 0; i < 16; i++) acc[i][0] = acc[i][1] = acc[i][2] = acc[i][3] = 0.f;
    const float* wrow = w1 + og * 16 * 64;
#pragma unroll 4
    for (int c = 0; c < 64; c++) {
        float4 iv = *(const float4*)(ins + c * 68 + pg * 4);
#pragma unroll
        for (int i = 0; i < 16; i++) {
            float wv = __ldg(wrow + i * 64 + c);
            acc[i][0] += wv * iv.x; acc[i][1] += wv * iv.y;
            acc[i][2] += wv * iv.z; acc[i][3] += wv * iv.w;
        }
    }
    float* ybase = g_y + (uv * 256 + og * 16) * PL + p0 + pg * 4;
#pragma unroll
    for (int i = 0; i < 16; i++) {
        float bb = __ldg(b1 + og * 16 + i);
        float4 o; float a;
        a = acc[i][0] + bb; o.x = a / (1.f + __expf(-a));
        a = acc[i][1] + bb; o.y = a / (1.f + __expf(-a));
        a = acc[i][2] + bb; o.z = a / (1.f + __expf(-a));
        a = acc[i][3] + bb; o.w = a / (1.f + __expf(-a));
        *(float4*)(ybase + i * PL) = o;
    }
}

// depthwise 5x5, 32-row tiles
__global__ void k_dw(const float* __restrict__ dw, const float* __restrict__ db) {
    __shared__ float tile[36][132];
    int b = blockIdx.x;
    int plane = b >> 2, h0 = (b & 3) * 32;
    int ch = plane & 255;
    const float* src = g_y + plane * PL;
    int tid = threadIdx.x;
    for (int i = tid; i < 36 * 132; i += 256) {
        int rr = i / 132, cc = i % 132;
        int h = h0 + rr - 2, w = cc - 2;
        tile[rr][cc] = (h >= 0 && h < 128 && w >= 0 && w < 128) ? src[h * 128 + w] : 0.f;
    }
    __syncthreads();
    float wr[25];
#pragma unroll
    for (int k = 0; k < 25; k++) wr[k] = __ldg(dw + ch * 25 + k);
    float bb = __ldg(db + ch);
    int w = tid & 127, hs = tid >> 7;
#pragma unroll 4
    for (int r = hs; r < 32; r += 2) {
        float a = bb;
#pragma unroll
        for (int dy = 0; dy < 5; dy++)
#pragma unroll
            for (int dx = 0; dx < 5; dx++)
                a += wr[dy * 5 + dx] * tile[r + dy][w + dx];
        g_z[plane * PL + (h0 + r) * 128 + w] = a / (1.f + __expf(-a));
    }
}

__global__ void k_proj(const float* __restrict__ w2, const float* __restrict__ b2,
                       float* __restrict__ out) {
    __shared__ float ins[64 * 132];
    int b = blockIdx.x;
    int uv = b >> 7, p0 = (b & 127) * 128;
    int tid = threadIdx.x;
    int pg = tid & 31, og = tid >> 5;
    float acc[8][4];
#pragma unroll
    for (int i = 0; i < 8; i++) acc[i][0] = acc[i][1] = acc[i][2] = acc[i][3] = 0.f;
    for (int kc = 0; kc < 4; kc++) {
        __syncthreads();
        for (int i = tid; i < 2048; i += 256) {
            int k = i >> 5, pl4 = i & 31;
            *(float4*)(ins + k * 132 + pl4 * 4) =
                *(const float4*)(g_z + (uv * 256 + kc * 64 + k) * PL + p0 + pl4 * 4);
        }
        __syncthreads();
#pragma unroll 4
        for (int k = 0; k < 64; k++) {
            float4 iv = *(const float4*)(ins + k * 132 + pg * 4);
#pragma unroll
            for (int i = 0; i < 8; i++) {
                float wv = __ldg(w2 + (og * 8 + i) * 256 + kc * 64 + k);
                acc[i][0] += wv * iv.x; acc[i][1] += wv * iv.y;
                acc[i][2] += wv * iv.z; acc[i][3] += wv * iv.w;
            }
        }
    }
#pragma unroll
    for (int i = 0; i < 8; i++) {
        int oc = og * 8 + i;
        float bb = __ldg(b2 + oc);
        int g = (uv * 64 + oc) * PL + p0 + pg * 4;
        float4 xv = *(const float4*)(g_x1 + g);
        float4 o;
        o.x = acc[i][0] + bb + xv.x; o.y = acc[i][1] + bb + xv.y;
        o.z = acc[i][2] + bb + xv.z; o.w = acc[i][3] + bb + xv.w;
        *(float4*)(out + g) = o;
    }
}

extern "C" void kernel_launch(void* const* d_in, const int* in_sizes, int n_in,
                              void* d_out, int out_size) {
    (void)in_sizes; (void)n_in; (void)out_size;
    const float* x    = (const float*)d_in[0];
    const float* n1w  = (const float*)d_in[1];
    const float* n1b  = (const float*)d_in[2];
    const float* n2w  = (const float*)d_in[3];
    const float* n2b  = (const float*)d_in[4];
    const float* qkvw = (const float*)d_in[5];
    const float* qkvb = (const float*)d_in[6];
    const float* pw   = (const float*)d_in[7];
    const float* pb   = (const float*)d_in[8];
    const float* rpb  = (const float*)d_in[9];
    const int*   rpi  = (const int*)d_in[10];
    const float* mw1  = (const float*)d_in[11];
    const float* mb1  = (const float*)d_in[12];
    const float* mw2  = (const float*)d_in[13];
    const float* mb2  = (const float*)d_in[14];
    const float* mfw  = (const float*)d_in[15];
    const float* mfb  = (const float*)d_in[16];
    const float* ew1  = (const float*)d_in[17];
    const float* eb1  = (const float*)d_in[18];
    const float* edw  = (const float*)d_in[19];
    const float* edb  = (const float*)d_in[20];
    const float* ew2  = (const float*)d_in[21];
    const float* eb2  = (const float*)d_in[22];
    float* out = (float*)d_out;

    cudaFuncSetAttribute(k_attn, cudaFuncAttributeMaxDynamicSharedMemorySize, 94592);

    k_bias<<<64, 256>>>(rpb, rpi);
    k_ln1<<<1600, 256>>>(x, n1w, n1b);
    k_attn<<<6400, 256, 94592>>>(qkvw, qkvb, pw, pb);
    k_pool_hw<<<4096, 256>>>();
    k_pool_uv<<<1600, 256>>>();
    k_pool_hu<<<160, 256>>>();
    k_pool_vw<<<160, 256>>>();
    k_mca_conv<<<277, 256>>>(mw1, mb1, mw2, mb2);
    k_mca_fuse<<<277, 256>>>(mfw, mfb);
    k_addln<<<1600, 256>>>(x, n2w, n2b);
    k_expand<<<6400, 256>>>(ew1, eb1);
    k_dw<<<25600, 256>>>(edw, edb);
    k_proj<<<3200, 256>>>(ew2, eb2, out);
}